// round 12
// baseline (speedup 1.0000x reference)
#include <cuda_runtime.h>

#define NN 768
#define NF 128
#define MF 256
#define GF 256
#define ALPHA 0.01f
#define INV_CNT (1.0f / (NN * NF))

typedef unsigned long long ull;

// ---------------- scratch (no allocations allowed) ----------------
__device__ __align__(16) float g_msg[NN * MF];      // nodes @ we
__device__ __align__(16) float g_ebarp[3][NN * MF]; // partial ebar (j-thirds)
__device__ __align__(16) float g_pre[NN * NF];      // pre-layernorm new_nodes
__device__ float g_stats[2];                        // sum, sumsq
__device__ float g_colsum[NF];                      // column sums of g_pre

__device__ __forceinline__ float leaky(float x) { return fmaxf(x, ALPHA * x); }

// ---- packed f32x2 helpers (kept packed through the whole j-loop) ----
__device__ __forceinline__ ull dup2(float x) {
    ull r; asm("mov.b64 %0, {%1, %1};" : "=l"(r) : "f"(x)); return r;
}
__device__ __forceinline__ float2 unpack2(ull v) {
    float2 r; asm("mov.b64 {%0, %1}, %2;" : "=f"(r.x), "=f"(r.y) : "l"(v)); return r;
}
__device__ __forceinline__ ull fma2(ull a, ull b, ull c) {
    ull d; asm("fma.rn.f32x2 %0, %1, %2, %3;" : "=l"(d) : "l"(a), "l"(b), "l"(c)); return d;
}
__device__ __forceinline__ ull add2(ull a, ull b) {
    ull d; asm("add.rn.f32x2 %0, %1, %2;" : "=l"(d) : "l"(a), "l"(b)); return d;
}
__device__ __forceinline__ ull abs2(ull a) {            // clear both sign bits (2x LOP3, alu)
    return a & 0x7FFFFFFF7FFFFFFFULL;
}

// ---------------- K1: msg = nodes @ we  (768x128 @ 128x256) ----------------
// 96 blocks x 256 threads; block = 8 rows x 256 cols. Also zeroes reducers.
__global__ void k1_msg(const float* __restrict__ nodes, const float* __restrict__ we) {
    __shared__ float ns[8][NF];
    const int tx = threadIdx.x;
    const int i0 = blockIdx.x * 8;

    if (blockIdx.x == 0) {
        if (tx < 2) g_stats[tx] = 0.0f;
        if (tx < NF) g_colsum[tx] = 0.0f;
    }

    for (int t = tx; t < 8 * NF; t += 256) {
        ns[t >> 7][t & 127] = nodes[i0 * NF + t];
    }
    __syncthreads();

    float acc[8];
#pragma unroll
    for (int r = 0; r < 8; r++) acc[r] = 0.0f;

    for (int c = 0; c < NF; c++) {
        const float w = we[c * MF + tx];
#pragma unroll
        for (int r = 0; r < 8; r++) acc[r] = fmaf(ns[r][c], w, acc[r]);
    }
#pragma unroll
    for (int r = 0; r < 8; r++) g_msg[(i0 + r) * MF + tx] = acc[r];
}

// ---------------- K2: partial ebar over a j-third --------------------------
// leaky(t) = 0.505*t + 0.495*|t| (exact for alpha=0.01).
// grid (96, 2, 3): bx = 8-row i-tile, by = k-half, bz = j-third (256 js).
// 576 blocks, all resident (~3.9 warps/SMSP). Double-buffered cp.async.
// Packed f32x2 inner loop: per row-pair  FFMA2 + 2x FADD2 (fma pipe) +
// and.b64 abs (alu). 3 fma-inst / 2 elements, no pack/unpack in the loop:
// e-pairs come straight from smem as LDS.64 (row stride 48B, 8B-aligned).
#define TI 8
#define TJ 32
#define JT 256
#define NT (JT / TJ)   // 8 tiles per third

__device__ __forceinline__ void k2_fill(float (*ms)[128], float (*es)[12],
                                        const float* __restrict__ edges,
                                        int jt, int i0, int kbase,
                                        int jr, int c4, int jc, int rg) {
    const float4* msrc = reinterpret_cast<const float4*>(g_msg + (size_t)jt * MF + kbase);
    const unsigned mdst = (unsigned)__cvta_generic_to_shared(&ms[0][0]);
#pragma unroll
    for (int p = 0; p < 8; p++) {
        const int j = p * 4 + jr;
        asm volatile("cp.async.cg.shared.global [%0], [%1], 16;"
                     :: "r"(mdst + (unsigned)((j * 128 + c4 * 4) * 4)),
                        "l"(msrc + (size_t)j * (MF / 4) + c4));
    }
    const unsigned edst = (unsigned)__cvta_generic_to_shared(&es[jc][0]);
#pragma unroll
    for (int rr = 0; rr < 2; rr++) {
        asm volatile("cp.async.ca.shared.global [%0], [%1], 4;"
                     :: "r"(edst + (unsigned)((rg + rr) * 4)),
                        "l"(edges + (size_t)(i0 + rg + rr) * NN + jt + jc));
    }
    asm volatile("cp.async.commit_group;" ::: "memory");
}

__global__ void __launch_bounds__(128) k2_ebar(const float* __restrict__ edges,
                                               const float* __restrict__ b) {
    __shared__ __align__(16) float ms[2][TJ][128];  // 2x16KB msg tiles
    __shared__ __align__(16) float es[2][TJ][12];   // edge tiles (48B rows, 8B-aligned)
    const int tx = threadIdx.x;
    const int kbase = blockIdx.y * 128;
    const int k  = kbase + tx;
    const int i0 = blockIdx.x * TI;
    const int j0 = blockIdx.z * JT;
    const ull b2 = dup2(b[k]);
    const int c4 = tx & 31;          // msg-fill float4 column
    const int jr = tx >> 5;          // msg-fill row offset 0..3
    const int jc = tx & 31;          // edge-fill column 0..31
    const int rg = (tx >> 5) * 2;    // edge-fill row group (0,2,4,6)

    ull acc_t[4], acc_a[4];          // packed row-pairs (r=2p, 2p+1)
#pragma unroll
    for (int p = 0; p < 4; p++) { acc_t[p] = 0ULL; acc_a[p] = 0ULL; }

    k2_fill(ms[0], es[0], edges, j0, i0, kbase, jr, c4, jc, rg);

    for (int t = 0; t < NT; t++) {
        if (t + 1 < NT) {
            k2_fill(ms[(t + 1) & 1], es[(t + 1) & 1], edges,
                    j0 + (t + 1) * TJ, i0, kbase, jr, c4, jc, rg);
            asm volatile("cp.async.wait_group 1;" ::: "memory");
        } else {
            asm volatile("cp.async.wait_group 0;" ::: "memory");
        }
        __syncthreads();

        const float (*msb)[128] = ms[t & 1];
        const float (*esb)[12]  = es[t & 1];
#pragma unroll 4
        for (int j = 0; j < TJ; j++) {
            const float m = msb[j][tx];                   // bank-clean LDS
            const ull m2 = dup2(m);                       // 1 mov.b64 per 8 elems
            const ull* ep = reinterpret_cast<const ull*>(&esb[j][0]);  // LDS.64 x4
            const ull e01 = ep[0], e23 = ep[1], e45 = ep[2], e67 = ep[3];
            const ull t01 = fma2(m2, e01, b2);
            const ull t23 = fma2(m2, e23, b2);
            const ull t45 = fma2(m2, e45, b2);
            const ull t67 = fma2(m2, e67, b2);
            acc_t[0] = add2(acc_t[0], t01);  acc_a[0] = add2(acc_a[0], abs2(t01));
            acc_t[1] = add2(acc_t[1], t23);  acc_a[1] = add2(acc_a[1], abs2(t23));
            acc_t[2] = add2(acc_t[2], t45);  acc_a[2] = add2(acc_a[2], abs2(t45));
            acc_t[3] = add2(acc_t[3], t67);  acc_a[3] = add2(acc_a[3], abs2(t67));
        }
        __syncthreads();   // all warps done with buffer (t&1) before tile t+2 refills it
    }
#pragma unroll
    for (int p = 0; p < 4; p++) {
        const float2 vt = unpack2(acc_t[p]);
        const float2 va = unpack2(acc_a[p]);
        g_ebarp[blockIdx.z][(i0 + 2 * p)     * MF + k] = fmaf(0.495f, va.x, 0.505f * vt.x);
        g_ebarp[blockIdx.z][(i0 + 2 * p + 1) * MF + k] = fmaf(0.495f, va.y, 0.505f * vt.y);
    }
}

// ---------------- K3: pre = leaky((sum of ebar partials) @ wv) + nodes -----
// 192 blocks x 128 threads; block = 4 rows x 128 cols.
__global__ void k3_pre(const float* __restrict__ nodes, const float* __restrict__ wv) {
    __shared__ float eb[4][MF];
    __shared__ float red[128];
    const int tx = threadIdx.x;
    const int i0 = blockIdx.x * 4;

    for (int t = tx; t < 4 * MF; t += 128) {
        eb[t >> 8][t & 255] = g_ebarp[0][i0 * MF + t] + g_ebarp[1][i0 * MF + t]
                            + g_ebarp[2][i0 * MF + t];
    }
    __syncthreads();

    float acc[4];
#pragma unroll
    for (int r = 0; r < 4; r++) acc[r] = 0.0f;

    for (int c = 0; c < MF; c++) {
        const float w = wv[c * NF + tx];
#pragma unroll
        for (int r = 0; r < 4; r++) acc[r] = fmaf(eb[r][c], w, acc[r]);
    }

    float lsum = 0.0f, lss = 0.0f;
#pragma unroll
    for (int r = 0; r < 4; r++) {
        const float v = leaky(acc[r]) + nodes[(i0 + r) * NF + tx];
        g_pre[(i0 + r) * NF + tx] = v;
        lsum += v;
        lss = fmaf(v, v, lss);
    }
    atomicAdd(&g_colsum[tx], lsum);   // thread tx owns column tx

    // block-reduce sum and sumsq
    red[tx] = lsum;
    __syncthreads();
    for (int s = 64; s > 0; s >>= 1) {
        if (tx < s) red[tx] += red[tx + s];
        __syncthreads();
    }
    if (tx == 0) atomicAdd(&g_stats[0], red[0]);
    __syncthreads();
    red[tx] = lss;
    __syncthreads();
    for (int s = 64; s > 0; s >>= 1) {
        if (tx < s) red[tx] += red[tx + s];
        __syncthreads();
    }
    if (tx == 0) atomicAdd(&g_stats[1], red[0]);
}

// ---------------- K45: fused normalize + features -------------------------
// grid 104 x 256 threads. Blocks 0..95: normalize g_pre -> out_nodes (float4).
// Blocks 96..103: features, 256 threads each (8 c-chunks x 32 outputs).
__global__ void k45(const float* __restrict__ features, const float* __restrict__ wu,
                    float4* __restrict__ out_nodes, float* __restrict__ out_feat) {
    const float mu = g_stats[0] * INV_CNT;
    const float var = g_stats[1] * INV_CNT - mu * mu;
    const float rs = rsqrtf(var + 1e-5f);
    const int bx = blockIdx.x;
    const int tx = threadIdx.x;

    if (bx < 96) {
        const int idx = bx * 256 + tx;
        const float4 v = reinterpret_cast<const float4*>(g_pre)[idx];
        float4 o;
        o.x = (v.x - mu) * rs;
        o.y = (v.y - mu) * rs;
        o.z = (v.z - mu) * rs;
        o.w = (v.w - mu) * rs;
        out_nodes[idx] = o;
    } else {
        __shared__ float gs[NF];
        __shared__ float part[8][32];
        if (tx < NF) gs[tx] = (g_colsum[tx] - (float)NN * mu) * rs;
        __syncthreads();
        const int o  = (bx - 96) * 32 + (tx & 31);
        const int ch = tx >> 5;                 // 0..7, 16 c's each
        float acc = 0.0f;
#pragma unroll
        for (int cc = 0; cc < 16; cc++) {
            const int c = ch * 16 + cc;
            acc = fmaf(gs[c], wu[c * GF + o], acc);
        }
        part[ch][tx & 31] = acc;
        __syncthreads();
        if (tx < 32) {
            float s = 0.0f;
#pragma unroll
            for (int c2 = 0; c2 < 8; c2++) s += part[c2][tx];
            out_feat[(bx - 96) * 32 + tx] = leaky(s) + features[(bx - 96) * 32 + tx];
        }
    }
}

// ---------------- launch ---------------------------------------------------
extern "C" void kernel_launch(void* const* d_in, const int* in_sizes, int n_in,
                              void* d_out, int out_size) {
    (void)in_sizes; (void)n_in; (void)out_size;
    const float* nodes    = (const float*)d_in[0];
    const float* edges    = (const float*)d_in[1];
    const float* features = (const float*)d_in[2];
    const float* we       = (const float*)d_in[3];
    const float* b        = (const float*)d_in[4];
    const float* wv       = (const float*)d_in[5];
    const float* wu       = (const float*)d_in[6];

    float* out       = (float*)d_out;
    float* out_nodes = out;                       // [768*128]
    float* out_edges = out + NN * NF;             // [768*768]
    float* out_feat  = out + NN * NF + NN * NN;   // [256]

    cudaMemcpyAsync(out_edges, edges, (size_t)NN * NN * sizeof(float),
                    cudaMemcpyDeviceToDevice);

    k1_msg<<<96, 256>>>(nodes, we);
    dim3 g2(96, 2, 3);
    k2_ebar<<<g2, 128>>>(edges, b);
    k3_pre<<<192, 128>>>(nodes, wv);
    k45<<<104, 256>>>(features, wu, (float4*)out_nodes, out_feat);
}

// round 15
// speedup vs baseline: 1.0735x; 1.0735x over previous
#include <cuda_runtime.h>

#define NN 768
#define NF 128
#define MF 256
#define GF 256
#define ALPHA 0.01f
#define INV_CNT (1.0f / (NN * NF))

// ---------------- scratch (no allocations allowed) ----------------
__device__ __align__(16) float g_msg[NN * MF];      // nodes @ we
__device__ __align__(16) float g_ebarp[3][NN * MF]; // partial ebar (j-thirds)
__device__ __align__(16) float g_pre[NN * NF];      // pre-layernorm new_nodes
__device__ float g_stats[2];                        // sum, sumsq
__device__ float g_colsum[NF];                      // column sums of g_pre

__device__ __forceinline__ float leaky(float x) { return fmaxf(x, ALPHA * x); }

// acc += t via FFMA with immediate multiplier (rt_SMSP=1 vs FADD rt=2). Exact.
#define ACC_IMM(a, t) asm("fma.rn.f32 %0, %1, 0f3F800000, %0;" : "+f"(a) : "f"(t))
// |t| on the ALU pipe (LOP3), freeing the fma pipe. Bit-exact fabsf.
__device__ __forceinline__ float fabs_alu(float x) {
    return __int_as_float(__float_as_int(x) & 0x7fffffff);
}

// ---------------- K1: msg = nodes @ we  (768x128 @ 128x256) ----------------
// 96 blocks x 256 threads; block = 8 rows x 256 cols. Also zeroes reducers.
__global__ void k1_msg(const float* __restrict__ nodes, const float* __restrict__ we) {
    __shared__ float ns[8][NF];
    const int tx = threadIdx.x;
    const int i0 = blockIdx.x * 8;

    if (blockIdx.x == 0) {
        if (tx < 2) g_stats[tx] = 0.0f;
        if (tx < NF) g_colsum[tx] = 0.0f;
    }

    for (int t = tx; t < 8 * NF; t += 256) {
        ns[t >> 7][t & 127] = nodes[i0 * NF + t];
    }
    __syncthreads();

    float acc[8];
#pragma unroll
    for (int r = 0; r < 8; r++) acc[r] = 0.0f;

    for (int c = 0; c < NF; c++) {
        const float w = we[c * MF + tx];
#pragma unroll
        for (int r = 0; r < 8; r++) acc[r] = fmaf(ns[r][c], w, acc[r]);
    }
#pragma unroll
    for (int r = 0; r < 8; r++) g_msg[(i0 + r) * MF + tx] = acc[r];
}

// ---------------- K2: partial ebar over a j-third --------------------------
// leaky(t) = 0.505*t + 0.495*|t| (exact for alpha=0.01).
// grid (96, 2, 3): bx = 8-row i-tile, by = k-half, bz = j-third (256 js).
// 576 blocks, all resident (~3.9 warps/SMSP). Double-buffered cp.async.
// Per element: FFMA(t) rt2 [fma] + LOP3 |t| rt2 [alu] + 2x FFMA-imm rt1 [fma]
//   -> fma-pipe 4 rt-cyc, alu 2 (parallel).
#define TI 8
#define TJ 32
#define JT 256
#define NT (JT / TJ)   // 8 tiles per third

__device__ __forceinline__ void k2_fill(float (*ms)[128], float (*es)[12],
                                        const float* __restrict__ edges,
                                        int jt, int i0, int kbase,
                                        int jr, int c4, int jc, int rg) {
    const float4* msrc = reinterpret_cast<const float4*>(g_msg + (size_t)jt * MF + kbase);
    const unsigned mdst = (unsigned)__cvta_generic_to_shared(&ms[0][0]);
#pragma unroll
    for (int p = 0; p < 8; p++) {
        const int j = p * 4 + jr;
        asm volatile("cp.async.cg.shared.global [%0], [%1], 16;"
                     :: "r"(mdst + (unsigned)((j * 128 + c4 * 4) * 4)),
                        "l"(msrc + (size_t)j * (MF / 4) + c4));
    }
    const unsigned edst = (unsigned)__cvta_generic_to_shared(&es[jc][0]);
#pragma unroll
    for (int rr = 0; rr < 2; rr++) {
        asm volatile("cp.async.ca.shared.global [%0], [%1], 4;"
                     :: "r"(edst + (unsigned)((rg + rr) * 4)),
                        "l"(edges + (size_t)(i0 + rg + rr) * NN + jt + jc));
    }
    asm volatile("cp.async.commit_group;" ::: "memory");
}

__global__ void __launch_bounds__(128) k2_ebar(const float* __restrict__ edges,
                                               const float* __restrict__ b) {
    __shared__ __align__(16) float ms[2][TJ][128];  // 2x16KB msg tiles
    __shared__ __align__(16) float es[2][TJ][12];   // edge tiles (padded rows)
    const int tx = threadIdx.x;
    const int kbase = blockIdx.y * 128;
    const int k  = kbase + tx;
    const int i0 = blockIdx.x * TI;
    const int j0 = blockIdx.z * JT;
    const float bk = b[k];
    const int c4 = tx & 31;          // msg-fill float4 column
    const int jr = tx >> 5;          // msg-fill row offset 0..3
    const int jc = tx & 31;          // edge-fill column 0..31
    const int rg = (tx >> 5) * 2;    // edge-fill row group (0,2,4,6)

    float acc_t[TI], acc_a[TI];
#pragma unroll
    for (int r = 0; r < TI; r++) { acc_t[r] = 0.0f; acc_a[r] = 0.0f; }

    k2_fill(ms[0], es[0], edges, j0, i0, kbase, jr, c4, jc, rg);

    for (int t = 0; t < NT; t++) {
        if (t + 1 < NT) {
            k2_fill(ms[(t + 1) & 1], es[(t + 1) & 1], edges,
                    j0 + (t + 1) * TJ, i0, kbase, jr, c4, jc, rg);
            asm volatile("cp.async.wait_group 1;" ::: "memory");
        } else {
            asm volatile("cp.async.wait_group 0;" ::: "memory");
        }
        __syncthreads();

        const float (*msb)[128] = ms[t & 1];
        const float (*esb)[12]  = es[t & 1];
#pragma unroll 8
        for (int j = 0; j < TJ; j++) {
            const float m = msb[j][tx];                                     // bank-clean LDS
            const float4 e0 = *reinterpret_cast<const float4*>(&esb[j][0]); // LDS.128 bcast
            const float4 e1 = *reinterpret_cast<const float4*>(&esb[j][4]);
            float t0 = fmaf(m, e0.x, bk);
            float t1 = fmaf(m, e0.y, bk);
            float t2 = fmaf(m, e0.z, bk);
            float t3 = fmaf(m, e0.w, bk);
            float t4 = fmaf(m, e1.x, bk);
            float t5 = fmaf(m, e1.y, bk);
            float t6 = fmaf(m, e1.z, bk);
            float t7 = fmaf(m, e1.w, bk);
            ACC_IMM(acc_t[0], t0);  ACC_IMM(acc_a[0], fabs_alu(t0));
            ACC_IMM(acc_t[1], t1);  ACC_IMM(acc_a[1], fabs_alu(t1));
            ACC_IMM(acc_t[2], t2);  ACC_IMM(acc_a[2], fabs_alu(t2));
            ACC_IMM(acc_t[3], t3);  ACC_IMM(acc_a[3], fabs_alu(t3));
            ACC_IMM(acc_t[4], t4);  ACC_IMM(acc_a[4], fabs_alu(t4));
            ACC_IMM(acc_t[5], t5);  ACC_IMM(acc_a[5], fabs_alu(t5));
            ACC_IMM(acc_t[6], t6);  ACC_IMM(acc_a[6], fabs_alu(t6));
            ACC_IMM(acc_t[7], t7);  ACC_IMM(acc_a[7], fabs_alu(t7));
        }
        __syncthreads();   // all warps done with buffer (t&1) before tile t+2 refills it
    }
#pragma unroll
    for (int r = 0; r < TI; r++) {
        g_ebarp[blockIdx.z][(i0 + r) * MF + k] =
            fmaf(0.495f, acc_a[r], 0.505f * acc_t[r]);
    }
}

// ---------------- K3: pre = leaky((sum of ebar partials) @ wv) + nodes -----
// 192 blocks x 128 threads; block = 4 rows x 128 cols.
__global__ void k3_pre(const float* __restrict__ nodes, const float* __restrict__ wv) {
    __shared__ float eb[4][MF];
    __shared__ float red[128];
    const int tx = threadIdx.x;
    const int i0 = blockIdx.x * 4;

    for (int t = tx; t < 4 * MF; t += 128) {
        eb[t >> 8][t & 255] = g_ebarp[0][i0 * MF + t] + g_ebarp[1][i0 * MF + t]
                            + g_ebarp[2][i0 * MF + t];
    }
    __syncthreads();

    float acc[4];
#pragma unroll
    for (int r = 0; r < 4; r++) acc[r] = 0.0f;

    for (int c = 0; c < MF; c++) {
        const float w = wv[c * NF + tx];
#pragma unroll
        for (int r = 0; r < 4; r++) acc[r] = fmaf(eb[r][c], w, acc[r]);
    }

    float lsum = 0.0f, lss = 0.0f;
#pragma unroll
    for (int r = 0; r < 4; r++) {
        const float v = leaky(acc[r]) + nodes[(i0 + r) * NF + tx];
        g_pre[(i0 + r) * NF + tx] = v;
        lsum += v;
        lss = fmaf(v, v, lss);
    }
    atomicAdd(&g_colsum[tx], lsum);   // thread tx owns column tx

    // block-reduce sum and sumsq
    red[tx] = lsum;
    __syncthreads();
    for (int s = 64; s > 0; s >>= 1) {
        if (tx < s) red[tx] += red[tx + s];
        __syncthreads();
    }
    if (tx == 0) atomicAdd(&g_stats[0], red[0]);
    __syncthreads();
    red[tx] = lss;
    __syncthreads();
    for (int s = 64; s > 0; s >>= 1) {
        if (tx < s) red[tx] += red[tx + s];
        __syncthreads();
    }
    if (tx == 0) atomicAdd(&g_stats[1], red[0]);
}

// ---------------- K45: fused normalize + features -------------------------
// grid 56 x 256 threads. Blocks 0..47: normalize g_pre -> out_nodes, 2
// float4/thread with both loads issued first (MLP=2). Blocks 48..55:
// features, 256 threads each (8 c-chunks x 32 outputs).
__global__ void k45(const float* __restrict__ features, const float* __restrict__ wu,
                    float4* __restrict__ out_nodes, float* __restrict__ out_feat) {
    const float mu = g_stats[0] * INV_CNT;
    const float var = g_stats[1] * INV_CNT - mu * mu;
    const float rs = rsqrtf(var + 1e-5f);
    const int bx = blockIdx.x;
    const int tx = threadIdx.x;

    if (bx < 48) {
        const int idx = bx * 512 + tx;
        const float4* src = reinterpret_cast<const float4*>(g_pre);
        const float4 v0 = src[idx];
        const float4 v1 = src[idx + 256];
        float4 o0, o1;
        o0.x = (v0.x - mu) * rs;  o0.y = (v0.y - mu) * rs;
        o0.z = (v0.z - mu) * rs;  o0.w = (v0.w - mu) * rs;
        o1.x = (v1.x - mu) * rs;  o1.y = (v1.y - mu) * rs;
        o1.z = (v1.z - mu) * rs;  o1.w = (v1.w - mu) * rs;
        out_nodes[idx] = o0;
        out_nodes[idx + 256] = o1;
    } else {
        __shared__ float gs[NF];
        __shared__ float part[8][32];
        if (tx < NF) gs[tx] = (g_colsum[tx] - (float)NN * mu) * rs;
        __syncthreads();
        const int o  = (bx - 48) * 32 + (tx & 31);
        const int ch = tx >> 5;                 // 0..7, 16 c's each
        float acc = 0.0f;
#pragma unroll
        for (int cc = 0; cc < 16; cc++) {
            const int c = ch * 16 + cc;
            acc = fmaf(gs[c], wu[c * GF + o], acc);
        }
        part[ch][tx & 31] = acc;
        __syncthreads();
        if (tx < 32) {
            float s = 0.0f;
#pragma unroll
            for (int c2 = 0; c2 < 8; c2++) s += part[c2][tx];
            out_feat[(bx - 48) * 32 + tx] = leaky(s) + features[(bx - 48) * 32 + tx];
        }
    }
}

// ---------------- launch ---------------------------------------------------
extern "C" void kernel_launch(void* const* d_in, const int* in_sizes, int n_in,
                              void* d_out, int out_size) {
    (void)in_sizes; (void)n_in; (void)out_size;
    const float* nodes    = (const float*)d_in[0];
    const float* edges    = (const float*)d_in[1];
    const float* features = (const float*)d_in[2];
    const float* we       = (const float*)d_in[3];
    const float* b        = (const float*)d_in[4];
    const float* wv       = (const float*)d_in[5];
    const float* wu       = (const float*)d_in[6];

    float* out       = (float*)d_out;
    float* out_nodes = out;                       // [768*128]
    float* out_edges = out + NN * NF;             // [768*768]
    float* out_feat  = out + NN * NF + NN * NN;   // [256]

    cudaMemcpyAsync(out_edges, edges, (size_t)NN * NN * sizeof(float),
                    cudaMemcpyDeviceToDevice);

    k1_msg<<<96, 256>>>(nodes, we);
    dim3 g2(96, 2, 3);
    k2_ebar<<<g2, 128>>>(edges, b);
    k3_pre<<<192, 128>>>(nodes, wv);
    k45<<<56, 256>>>(features, wu, (float4*)out_nodes, out_feat);
}

// round 16
// speedup vs baseline: 1.1054x; 1.0298x over previous
#include <cuda_runtime.h>

#define NN 768
#define NF 128
#define MF 256
#define GF 256
#define ALPHA 0.01f
#define INV_CNT (1.0f / (NN * NF))

// ---------------- scratch (no allocations allowed) ----------------
__device__ __align__(16) float g_msg[NN * MF];      // nodes @ we
__device__ __align__(16) float g_ebarp[3][NN * MF]; // partial ebar (j-thirds)
__device__ __align__(16) float g_pre[NN * NF];      // pre-layernorm new_nodes
__device__ float g_stats[2];                        // sum, sumsq
__device__ float g_colsum[NF];                      // column sums of g_pre

__device__ __forceinline__ float leaky(float x) { return fmaxf(x, ALPHA * x); }

// acc += t via FFMA with immediate multiplier (rt_SMSP=1 vs FADD rt=2). Exact.
#define ACC_IMM(a, t) asm("fma.rn.f32 %0, %1, 0f3F800000, %0;" : "+f"(a) : "f"(t))
// |t| on the ALU pipe (LOP3), freeing the fma pipe. Bit-exact fabsf.
__device__ __forceinline__ float fabs_alu(float x) {
    return __int_as_float(__float_as_int(x) & 0x7fffffff);
}

// ---------------- K1: msg = nodes @ we  (768x128 @ 128x256) ----------------
// 96 blocks x 256 threads; block = 8 rows x 256 cols. Also zeroes reducers.
__global__ void k1_msg(const float* __restrict__ nodes, const float* __restrict__ we) {
    __shared__ float ns[8][NF];
    const int tx = threadIdx.x;
    const int i0 = blockIdx.x * 8;

    if (blockIdx.x == 0) {
        if (tx < 2) g_stats[tx] = 0.0f;
        if (tx < NF) g_colsum[tx] = 0.0f;
    }

    for (int t = tx; t < 8 * NF; t += 256) {
        ns[t >> 7][t & 127] = nodes[i0 * NF + t];
    }
    __syncthreads();

    float acc[8];
#pragma unroll
    for (int r = 0; r < 8; r++) acc[r] = 0.0f;

    for (int c = 0; c < NF; c++) {
        const float w = we[c * MF + tx];
#pragma unroll
        for (int r = 0; r < 8; r++) acc[r] = fmaf(ns[r][c], w, acc[r]);
    }
#pragma unroll
    for (int r = 0; r < 8; r++) g_msg[(i0 + r) * MF + tx] = acc[r];
}

// ---------------- K2: partial ebar over a j-third --------------------------
// leaky(t) = 0.505*t + 0.495*|t| (exact for alpha=0.01).
// grid (96, 2, 3): bx = 8-row i-tile, by = k-half, bz = j-third (256 js).
// KEY: msg column k is THREAD-PRIVATE (thread tx only reads k = by*128+tx),
// so it streams straight into registers via coalesced LDG, software-pipelined
// 8-js ahead. Only the 8x256 edge slab is shared: loaded into smem ONCE
// (12KB, single sync). Main loop has NO syncs, NO cp.async.
// by==0 blocks also stream the edge slab to out_edges (replaces D2D memcpy).
#define TI 8
#define JT 256
#define JG 8    // j-group (prefetch granularity)

__global__ void __launch_bounds__(128) k2_ebar(const float* __restrict__ edges,
                                               const float* __restrict__ b,
                                               float* __restrict__ out_edges) {
    __shared__ __align__(16) float es[JT][12];   // es[j][row], 48B padded rows
    const int tx = threadIdx.x;
    const int k  = blockIdx.y * 128 + tx;
    const int i0 = blockIdx.x * TI;
    const int j0 = blockIdx.z * JT;
    const float bk = b[k];
    const bool wr = (blockIdx.y == 0);

    // ---- edge slab fill (one-time): 8 rows x 256 cols, coalesced ----
#pragma unroll
    for (int r = 0; r < TI; r++) {
#pragma unroll
        for (int h = 0; h < 2; h++) {
            const int jc = tx + h * 128;
            const float v = edges[(size_t)(i0 + r) * NN + j0 + jc];
            es[jc][r] = v;
            if (wr) out_edges[(size_t)(i0 + r) * NN + j0 + jc] = v;
        }
    }
    __syncthreads();   // the only sync in this kernel

    // ---- msg register pipeline ----
    const float* mcol = g_msg + j0 * MF + k;     // thread-private column, stride MF
    float mc[JG], mn[JG];
#pragma unroll
    for (int p = 0; p < JG; p++) mc[p] = __ldg(mcol + p * MF);

    float acc_t[TI], acc_a[TI];
#pragma unroll
    for (int r = 0; r < TI; r++) { acc_t[r] = 0.0f; acc_a[r] = 0.0f; }

    for (int jb = 0; jb < JT; jb += JG) {
        // prefetch next group (wrap keeps addresses in-bounds; values unused on last)
        const int jn = (jb + JG) & (JT - 1);
#pragma unroll
        for (int p = 0; p < JG; p++) mn[p] = __ldg(mcol + (jn + p) * MF);

#pragma unroll
        for (int p = 0; p < JG; p++) {
            const int j = jb + p;
            const float m = mc[p];
            const float4 e0 = *reinterpret_cast<const float4*>(&es[j][0]); // bcast LDS.128
            const float4 e1 = *reinterpret_cast<const float4*>(&es[j][4]);
            float t0 = fmaf(m, e0.x, bk);
            float t1 = fmaf(m, e0.y, bk);
            float t2 = fmaf(m, e0.z, bk);
            float t3 = fmaf(m, e0.w, bk);
            float t4 = fmaf(m, e1.x, bk);
            float t5 = fmaf(m, e1.y, bk);
            float t6 = fmaf(m, e1.z, bk);
            float t7 = fmaf(m, e1.w, bk);
            ACC_IMM(acc_t[0], t0);  ACC_IMM(acc_a[0], fabs_alu(t0));
            ACC_IMM(acc_t[1], t1);  ACC_IMM(acc_a[1], fabs_alu(t1));
            ACC_IMM(acc_t[2], t2);  ACC_IMM(acc_a[2], fabs_alu(t2));
            ACC_IMM(acc_t[3], t3);  ACC_IMM(acc_a[3], fabs_alu(t3));
            ACC_IMM(acc_t[4], t4);  ACC_IMM(acc_a[4], fabs_alu(t4));
            ACC_IMM(acc_t[5], t5);  ACC_IMM(acc_a[5], fabs_alu(t5));
            ACC_IMM(acc_t[6], t6);  ACC_IMM(acc_a[6], fabs_alu(t6));
            ACC_IMM(acc_t[7], t7);  ACC_IMM(acc_a[7], fabs_alu(t7));
        }
#pragma unroll
        for (int p = 0; p < JG; p++) mc[p] = mn[p];
    }
#pragma unroll
    for (int r = 0; r < TI; r++) {
        g_ebarp[blockIdx.z][(i0 + r) * MF + k] =
            fmaf(0.495f, acc_a[r], 0.505f * acc_t[r]);
    }
}

// ---------------- K3: pre = leaky((sum of ebar partials) @ wv) + nodes -----
// 192 blocks x 128 threads; block = 4 rows x 128 cols.
__global__ void k3_pre(const float* __restrict__ nodes, const float* __restrict__ wv) {
    __shared__ float eb[4][MF];
    __shared__ float red[128];
    const int tx = threadIdx.x;
    const int i0 = blockIdx.x * 4;

    for (int t = tx; t < 4 * MF; t += 128) {
        eb[t >> 8][t & 255] = g_ebarp[0][i0 * MF + t] + g_ebarp[1][i0 * MF + t]
                            + g_ebarp[2][i0 * MF + t];
    }
    __syncthreads();

    float acc[4];
#pragma unroll
    for (int r = 0; r < 4; r++) acc[r] = 0.0f;

    for (int c = 0; c < MF; c++) {
        const float w = wv[c * NF + tx];
#pragma unroll
        for (int r = 0; r < 4; r++) acc[r] = fmaf(eb[r][c], w, acc[r]);
    }

    float lsum = 0.0f, lss = 0.0f;
#pragma unroll
    for (int r = 0; r < 4; r++) {
        const float v = leaky(acc[r]) + nodes[(i0 + r) * NF + tx];
        g_pre[(i0 + r) * NF + tx] = v;
        lsum += v;
        lss = fmaf(v, v, lss);
    }
    atomicAdd(&g_colsum[tx], lsum);   // thread tx owns column tx

    // block-reduce sum and sumsq
    red[tx] = lsum;
    __syncthreads();
    for (int s = 64; s > 0; s >>= 1) {
        if (tx < s) red[tx] += red[tx + s];
        __syncthreads();
    }
    if (tx == 0) atomicAdd(&g_stats[0], red[0]);
    __syncthreads();
    red[tx] = lss;
    __syncthreads();
    for (int s = 64; s > 0; s >>= 1) {
        if (tx < s) red[tx] += red[tx + s];
        __syncthreads();
    }
    if (tx == 0) atomicAdd(&g_stats[1], red[0]);
}

// ---------------- K45: fused normalize + features -------------------------
// grid 56 x 256 threads. Blocks 0..47: normalize g_pre -> out_nodes, 2
// float4/thread with both loads issued first (MLP=2). Blocks 48..55:
// features, 256 threads each (8 c-chunks x 32 outputs).
__global__ void k45(const float* __restrict__ features, const float* __restrict__ wu,
                    float4* __restrict__ out_nodes, float* __restrict__ out_feat) {
    const float mu = g_stats[0] * INV_CNT;
    const float var = g_stats[1] * INV_CNT - mu * mu;
    const float rs = rsqrtf(var + 1e-5f);
    const int bx = blockIdx.x;
    const int tx = threadIdx.x;

    if (bx < 48) {
        const int idx = bx * 512 + tx;
        const float4* src = reinterpret_cast<const float4*>(g_pre);
        const float4 v0 = src[idx];
        const float4 v1 = src[idx + 256];
        float4 o0, o1;
        o0.x = (v0.x - mu) * rs;  o0.y = (v0.y - mu) * rs;
        o0.z = (v0.z - mu) * rs;  o0.w = (v0.w - mu) * rs;
        o1.x = (v1.x - mu) * rs;  o1.y = (v1.y - mu) * rs;
        o1.z = (v1.z - mu) * rs;  o1.w = (v1.w - mu) * rs;
        out_nodes[idx] = o0;
        out_nodes[idx + 256] = o1;
    } else {
        __shared__ float gs[NF];
        __shared__ float part[8][32];
        if (tx < NF) gs[tx] = (g_colsum[tx] - (float)NN * mu) * rs;
        __syncthreads();
        const int o  = (bx - 48) * 32 + (tx & 31);
        const int ch = tx >> 5;                 // 0..7, 16 c's each
        float acc = 0.0f;
#pragma unroll
        for (int cc = 0; cc < 16; cc++) {
            const int c = ch * 16 + cc;
            acc = fmaf(gs[c], wu[c * GF + o], acc);
        }
        part[ch][tx & 31] = acc;
        __syncthreads();
        if (tx < 32) {
            float s = 0.0f;
#pragma unroll
            for (int c2 = 0; c2 < 8; c2++) s += part[c2][tx];
            out_feat[(bx - 48) * 32 + tx] = leaky(s) + features[(bx - 48) * 32 + tx];
        }
    }
}

// ---------------- launch ---------------------------------------------------
extern "C" void kernel_launch(void* const* d_in, const int* in_sizes, int n_in,
                              void* d_out, int out_size) {
    (void)in_sizes; (void)n_in; (void)out_size;
    const float* nodes    = (const float*)d_in[0];
    const float* edges    = (const float*)d_in[1];
    const float* features = (const float*)d_in[2];
    const float* we       = (const float*)d_in[3];
    const float* b        = (const float*)d_in[4];
    const float* wv       = (const float*)d_in[5];
    const float* wu       = (const float*)d_in[6];

    float* out       = (float*)d_out;
    float* out_nodes = out;                       // [768*128]
    float* out_edges = out + NN * NF;             // [768*768]
    float* out_feat  = out + NN * NF + NN * NN;   // [256]

    k1_msg<<<96, 256>>>(nodes, we);
    dim3 g2(96, 2, 3);
    k2_ebar<<<g2, 128>>>(edges, b, out_edges);
    k3_pre<<<192, 128>>>(nodes, wv);
    k45<<<56, 256>>>(features, wu, (float4*)out_nodes, out_feat);
}